// round 2
// baseline (speedup 1.0000x reference)
#include <cuda_runtime.h>
#include <math.h>
#include <stdint.h>

#define NN 100000
#define NROWS 100096   // 782 * 128, padded for tiled GEMM
#define EE 1600000
#define BB 4096
#define ML 50

#define MIN_NORM 1e-15f
#define EPSC 1e-7f
#define MAX_NORMC 1000000.0f

// ---------------- persistent scratch (static device allocations) ----------------
__device__ float d_K, d_sqrtK;
__device__ float d_ub1[128], d_ubg1[128], d_ubg2[128];
__device__ float d_la  [(size_t)NROWS * 128];  // logmap0(a)
__device__ float d_t1p1[(size_t)NROWS * 256];  // GEMM outputs (t1 | p1) / q (stride 128)
__device__ float d_la1 [(size_t)NN * 128];     // logmap0(a1)
__device__ float d_la2 [(size_t)NN * 128];     // logmap0(a2)
__device__ float d_g   [(size_t)NN * 128];     // pre-aggregation tangent vectors
__device__ float d_agg [(size_t)NN * 128];     // segment-sum accumulator
__device__ float d_lx  [(size_t)NROWS * 128];  // logmap0(x_1) then logmap0(x_2)
__device__ float d_Wcat[128 * 256];            // [Lin1[1:,:] | gc1_w[1:,:]]

// ---------------- warp helpers ----------------
__device__ __forceinline__ float wsum(float v) {
#pragma unroll
    for (int o = 16; o > 0; o >>= 1) v += __shfl_xor_sync(0xffffffffu, v, o);
    return v;
}

__device__ __forceinline__ float sdot(const float* a, const float* b, int lane) {
    float s = a[1] * b[1] + a[2] * b[2] + a[3] * b[3];
    if (lane != 0) s += a[0] * b[0];
    return wsum(s);
}

// expmap0 + proj : raw tangent (comp0 ignored) -> hyperboloid point. Returns p0.
__device__ __forceinline__ float hpoint(const float in[4], float out[4], int lane,
                                        float K, float sqrtK) {
    float ss = sdot(in, in, lane);
    float xn = fmaxf(sqrtf(ss), MIN_NORM);
    float th = xn / sqrtK;
    float s  = sqrtK * sinhf(th) / xn;
#pragma unroll
    for (int i = 0; i < 4; i++) out[i] = s * in[i];
    float ss2 = sdot(out, out, lane);
    float p0  = sqrtf(fmaxf(K + ss2, EPSC));
    if (lane == 0) out[0] = p0;
    return p0;
}

__device__ __forceinline__ void logmap0p(const float p[4], float p0, float out[4],
                                         int lane, float sqrtK) {
    float ssp = sdot(p, p, lane);
    float yn  = fmaxf(sqrtf(ssp), MIN_NORM);
    float t   = fmaxf(p0 / sqrtK, 1.0f + EPSC);
    float sc  = sqrtK * acoshf(t) / yn;
#pragma unroll
    for (int i = 0; i < 4; i++) out[i] = sc * p[i];
    if (lane == 0) out[0] = 0.0f;
}

__device__ __forceinline__ float mobius_add_pt(const float p[4], float p0,
                                               const float* __restrict__ u,
                                               float out[4], int lane,
                                               float K, float sqrtK) {
    float uv[4];
#pragma unroll
    for (int i = 0; i < 4; i++) uv[i] = u[lane * 4 + i];
    float ssp   = sdot(p, p, lane);
    float yn    = fmaxf(sqrtf(ssp), MIN_NORM);
    float du    = sdot(p, uv, lane);
    float alpha = du / (yn * sqrtK);
    float beta  = alpha * (sqrtK - p0) / yn;
    float w[4];
#pragma unroll
    for (int i = 0; i < 4; i++) w[i] = uv[i] - beta * p[i];
    float ux = sdot(p, w, lane);
    float w0 = ux / fmaxf(p0, EPSC);
    float wss   = sdot(w, w, lane);
    float md    = wss - w0 * w0;
    float normu = fminf(sqrtf(fmaxf(md, EPSC)), MAX_NORMC);
    float th    = fmaxf(normu / sqrtK, MIN_NORM);
    float ch    = coshf(th);
    float sh    = sinhf(th) / th;
#pragma unroll
    for (int i = 0; i < 4; i++) out[i] = ch * p[i] + sh * w[i];
    float rss = sdot(out, out, lane);
    float q0  = sqrtf(fmaxf(K + rss, EPSC));
    if (lane == 0) out[0] = q0;
    return q0;
}

// ---------------- K0: constants + bias tangent vectors ----------------
__device__ void bias_u(const float* b, float* u, float K, float sqrtK) {
    float ss = 0.0f;
    for (int i = 1; i < 128; i++) ss += b[i] * b[i];
    float xn = fmaxf(sqrtf(ss), MIN_NORM);
    float th = xn / sqrtK;
    float s  = sqrtK * sinhf(th) / xn;
    float y[128];
    float ss2 = 0.0f;
    for (int i = 1; i < 128; i++) { y[i] = s * b[i]; ss2 += y[i] * y[i]; }
    float x0 = sqrtf(fmaxf(K + ss2, EPSC));
    float yn = fmaxf(sqrtf(ss2), MIN_NORM);
    float t  = fmaxf(x0 / sqrtK, 1.0f + EPSC);
    float sc = sqrtK * acoshf(t) / yn;
    u[0] = 0.0f;
    for (int i = 1; i < 128; i++) u[i] = sc * y[i];
}

__global__ void k0(const float* __restrict__ rc, const float* __restrict__ b1,
                   const float* __restrict__ bg1, const float* __restrict__ bg2) {
    float c = log1pf(expf(rc[0])) + 1e-5f;
    float K = 1.0f / c, sq = sqrtf(K);
    d_K = K; d_sqrtK = sq;
    bias_u(b1,  d_ub1,  K, sq);
    bias_u(bg1, d_ubg1, K, sq);
    bias_u(bg2, d_ubg2, K, sq);
}

__global__ void prep_wcat(const float* __restrict__ Lin1, const float* __restrict__ g1w) {
    int j = blockIdx.x * 256 + threadIdx.x;
    int k = j >> 8, col = j & 255;
    d_Wcat[j] = (col < 128) ? Lin1[(k + 1) * 128 + col]
                            : g1w[(k + 1) * 128 + (col - 128)];
}

// ---------------- K1: la = logmap0(proj(expmap0(A1 spatial))) ----------------
__global__ void __launch_bounds__(256) k1(const float* __restrict__ A1) {
    int node = blockIdx.x * 8 + (threadIdx.x >> 5);
    int lane = threadIdx.x & 31;
    float K = d_K, sq = d_sqrtK;
    const float* row = A1 + (size_t)node * 129 + 1;
    float x[4];
#pragma unroll
    for (int i = 0; i < 4; i++) x[i] = row[lane * 4 + i];
    float ss = wsum(x[0]*x[0] + x[1]*x[1] + x[2]*x[2] + x[3]*x[3]);
    float xn = fmaxf(sqrtf(ss), MIN_NORM);
    float th = xn / sq;
    float s  = sq * sinhf(th) / xn;
    float y[4];
#pragma unroll
    for (int i = 0; i < 4; i++) y[i] = s * x[i];
    float ss2 = wsum(y[0]*y[0] + y[1]*y[1] + y[2]*y[2] + y[3]*y[3]);
    float x0 = sqrtf(fmaxf(K + ss2, EPSC));
    float yn = fmaxf(sqrtf(ss2), MIN_NORM);
    float t  = fmaxf(x0 / sq, 1.0f + EPSC);
    float sc = sq * acoshf(t) / yn;
    float* o = d_la + (size_t)node * 128 + lane * 4;
#pragma unroll
    for (int i = 0; i < 4; i++) o[i] = sc * y[i];
}

// ---------------- register-blocked SGEMM: (NROWS,128) @ (128,N) ----------------
// BM=128, BN=128, BK=32, 256 threads, 8x8 micro-tile.
__global__ void __launch_bounds__(256) sgemm(const float* __restrict__ A,
                                             const float* __restrict__ W,
                                             float* __restrict__ C, int N) {
    __shared__ float sA[32][128];   // [k][m]
    __shared__ float sB[32][128];   // [k][n]

    int tid = threadIdx.x;
    int tx = tid & 15;        // 0..15  -> col group
    int ty = tid >> 4;        // 0..15  -> row group
    int r0 = blockIdx.x * 128;
    int n0 = blockIdx.y * 128;

    // A-load mapping: row = tid>>1 (0..127), 4 float4 each
    int arow = tid >> 1;
    int af   = (tid & 1) * 4;   // float4 index base (0 or 4) of 8 per row
    // B-load mapping: krow = tid>>3 (0..31), 4 float4 each
    int brow = tid >> 3;
    int bf   = (tid & 7) * 4;

    float acc[8][8];
#pragma unroll
    for (int i = 0; i < 8; i++)
#pragma unroll
        for (int j = 0; j < 8; j++) acc[i][j] = 0.0f;

    for (int k0 = 0; k0 < 128; k0 += 32) {
        // load A tile (128 rows x 32 k), transpose into sA[k][m]
#pragma unroll
        for (int i = 0; i < 4; i++) {
            int f = af + i;                       // 0..7
            float4 v = *(const float4*)(A + (size_t)(r0 + arow) * 128 + k0 + f * 4);
            sA[f * 4 + 0][arow] = v.x;
            sA[f * 4 + 1][arow] = v.y;
            sA[f * 4 + 2][arow] = v.z;
            sA[f * 4 + 3][arow] = v.w;
        }
        // load B tile (32 k x 128 n)
#pragma unroll
        for (int i = 0; i < 4; i++) {
            int f = bf + i;                       // 0..31
            float4 v = *(const float4*)(W + (size_t)(k0 + brow) * N + n0 + f * 4);
            *(float4*)&sB[brow][f * 4] = v;
        }
        __syncthreads();

#pragma unroll 8
        for (int kk = 0; kk < 32; kk++) {
            float a[8], b[8];
            *(float4*)&a[0] = *(const float4*)&sA[kk][ty * 8];
            *(float4*)&a[4] = *(const float4*)&sA[kk][ty * 8 + 4];
            *(float4*)&b[0] = *(const float4*)&sB[kk][tx * 8];
            *(float4*)&b[4] = *(const float4*)&sB[kk][tx * 8 + 4];
#pragma unroll
            for (int i = 0; i < 8; i++)
#pragma unroll
                for (int j = 0; j < 8; j++)
                    acc[i][j] = fmaf(a[i], b[j], acc[i][j]);
        }
        __syncthreads();
    }

    // store 8x8 block
#pragma unroll
    for (int i = 0; i < 8; i++) {
        float* dst = C + (size_t)(r0 + ty * 8 + i) * N + n0 + tx * 8;
        *(float4*)dst       = *(float4*)&acc[i][0];
        *(float4*)(dst + 4) = *(float4*)&acc[i][4];
    }
}

__global__ void __launch_bounds__(256) gemm1_entry() { }  // unused placeholder

// ---------------- K3: a1, a2 logs + layer-1 pre-aggregation tangents ----------------
__global__ void __launch_bounds__(256) k3(const float* __restrict__ nparam) {
    int node = blockIdx.x * 8 + (threadIdx.x >> 5);
    int lane = threadIdx.x & 31;
    float K = d_K, sq = d_sqrtK;
    const float* tr = d_t1p1 + (size_t)node * 256;
    float t[4], p[4];
#pragma unroll
    for (int i = 0; i < 4; i++) { t[i] = tr[lane * 4 + i]; p[i] = tr[128 + lane * 4 + i]; }

    float P[4];  float p0 = hpoint(t, P, lane, K, sq);
    float Aa[4]; float a0 = mobius_add_pt(P, p0, d_ub1, Aa, lane, K, sq);
    float l1[4]; logmap0p(Aa, a0, l1, lane, sq);
    float* o1 = d_la1 + (size_t)node * 128 + lane * 4;
#pragma unroll
    for (int i = 0; i < 4; i++) o1[i] = l1[i];

    float n = nparam[node];
    float v2[4];
#pragma unroll
    for (int i = 0; i < 4; i++) v2[i] = n * l1[i];
    float A2[4]; float a20 = hpoint(v2, A2, lane, K, sq);
    float l2[4]; logmap0p(A2, a20, l2, lane, sq);
    float* o2 = d_la2 + (size_t)node * 128 + lane * 4;
#pragma unroll
    for (int i = 0; i < 4; i++) o2[i] = l2[i];

    float Pg[4]; float pg0 = hpoint(p, Pg, lane, K, sq);
    float G[4];  float g0  = mobius_add_pt(Pg, pg0, d_ubg1, G, lane, K, sq);
    float lg[4]; logmap0p(G, g0, lg, lane, sq);
    float* og = d_g + (size_t)node * 128 + lane * 4;
#pragma unroll
    for (int i = 0; i < 4; i++) og[i] = lg[i];
}

// ---------------- zero + SpMM (segment_sum via vector atomics) ----------------
__global__ void zero_agg() {
    size_t i = (size_t)blockIdx.x * blockDim.x + threadIdx.x;
    float4 z = make_float4(0.f, 0.f, 0.f, 0.f);
    size_t total = (size_t)NN * 32;
    for (; i < total; i += (size_t)gridDim.x * blockDim.x) ((float4*)d_agg)[i] = z;
}

__global__ void __launch_bounds__(256) spmm(const int* __restrict__ rows,
                                            const int* __restrict__ cols,
                                            const float* __restrict__ vals) {
    int e = blockIdx.x * 8 + (threadIdx.x >> 5);
    int lane = threadIdx.x & 31;
    int cI = cols[e], rI = rows[e];
    float v = vals[e];
    float4 g = ((const float4*)(d_g + (size_t)cI * 128))[lane];
    float4* dst = ((float4*)(d_agg + (size_t)rI * 128)) + lane;
    asm volatile("red.global.add.v4.f32 [%0], {%1,%2,%3,%4};"
                 :: "l"(dst), "f"(g.x * v), "f"(g.y * v), "f"(g.z * v), "f"(g.w * v)
                 : "memory");
}

// ---------------- K7: x_1 assembly; store logmap0(x_1) ----------------
__global__ void __launch_bounds__(256) k7(const float* __restrict__ nparam) {
    int node = blockIdx.x * 8 + (threadIdx.x >> 5);
    int lane = threadIdx.x & 31;
    float K = d_K, sq = d_sqrtK;
    const float* ar = d_agg + (size_t)node * 128 + lane * 4;
    float v[4];
#pragma unroll
    for (int i = 0; i < 4; i++) v[i] = ar[i];
    float X[4]; float x0 = hpoint(v, X, lane, K, sq);
    float l[4]; logmap0p(X, x0, l, lane, sq);
    float n = 1.0f - nparam[node];
    float v2[4];
#pragma unroll
    for (int i = 0; i < 4; i++) v2[i] = n * l[i];
    float X2[4]; float x20 = hpoint(v2, X2, lane, K, sq);
    float l2[4]; logmap0p(X2, x20, l2, lane, sq);
    const float* a2r = d_la2 + (size_t)node * 128 + lane * 4;
    float w[4];
#pragma unroll
    for (int i = 0; i < 4; i++) w[i] = l2[i] + a2r[i];
    float X3[4]; float x30 = hpoint(w, X3, lane, K, sq);
    float lx[4]; logmap0p(X3, x30, lx, lane, sq);
    float* o = d_lx + (size_t)node * 128 + lane * 4;
#pragma unroll
    for (int i = 0; i < 4; i++) o[i] = lx[i];
}

// ---------------- K9: layer-2 pre-aggregation tangents ----------------
__global__ void __launch_bounds__(256) k9() {
    int node = blockIdx.x * 8 + (threadIdx.x >> 5);
    int lane = threadIdx.x & 31;
    float K = d_K, sq = d_sqrtK;
    const float* qr = d_t1p1 + (size_t)node * 128 + lane * 4;
    float q[4];
#pragma unroll
    for (int i = 0; i < 4; i++) q[i] = qr[i];
    float X[4]; float x0 = hpoint(q, X, lane, K, sq);
    float G[4]; float g0 = mobius_add_pt(X, x0, d_ubg2, G, lane, K, sq);
    float lg[4]; logmap0p(G, g0, lg, lane, sq);
    float* o = d_g + (size_t)node * 128 + lane * 4;
#pragma unroll
    for (int i = 0; i < 4; i++) o[i] = lg[i];
}

// ---------------- K11: lx2 = logmap0(x_2) ----------------
__global__ void __launch_bounds__(256) k11() {
    int node = blockIdx.x * 8 + (threadIdx.x >> 5);
    int lane = threadIdx.x & 31;
    float K = d_K, sq = d_sqrtK;
    const float* ar = d_agg + (size_t)node * 128 + lane * 4;
    float v[4];
#pragma unroll
    for (int i = 0; i < 4; i++) v[i] = ar[i];
    float X[4]; float x0 = hpoint(v, X, lane, K, sq);
    float lx[4]; logmap0p(X, x0, lx, lane, sq);
    float* o = d_lx + (size_t)node * 128 + lane * 4;
#pragma unroll
    for (int i = 0; i < 4; i++) o[i] = lx[i];
}

// ---------------- head ----------------
__global__ void __launch_bounds__(128) head(const int* __restrict__ bidx,
                                            const float* __restrict__ wt,
                                            const float* __restrict__ wt2,
                                            const float* __restrict__ c1w,
                                            const float* __restrict__ c1b,
                                            const float* __restrict__ c2w,
                                            const float* __restrict__ c2b,
                                            const float* __restrict__ cls,
                                            const float* __restrict__ clsb,
                                            float* __restrict__ out) {
    int b = blockIdx.x;
    int d = threadIdx.x;
    __shared__ float sg2[128], sg3[128], sel[100];
    float g2 = 0.0f, g3 = 0.0f;
    const int* bi = bidx + (size_t)b * ML;
    for (int l = 0; l < ML; l++) {
        int idx = bi[l];
        float w1 = c1w[l], w2 = c2w[l];
        g2 = fmaf(w1, d_lx [(size_t)idx * 128 + d], g2);
        g3 = fmaf(w2, d_la1[(size_t)idx * 128 + d], g3);
    }
    sg2[d] = g2; sg3[d] = g3;
    __syncthreads();
    if (d < ML) {
        float s2 = c1b[0], s3 = c2b[0];
        for (int k = 0; k < 128; k++) {
            s2 = fmaf(sg2[k], wt [k * ML + d], s2);
            s3 = fmaf(sg3[k], wt2[k * ML + d], s3);
        }
        sel[d]      = s2;
        sel[ML + d] = s3;
        out[BB + (size_t)b * 100 + d]      = s2;
        out[BB + (size_t)b * 100 + ML + d] = s3;
    }
    __syncthreads();
    if (d == 0) {
        float best = -3.4e38f;
        int bj = 0;
        for (int j = 0; j < 5; j++) {
            float p = clsb[j];
            for (int i = 0; i < 100; i++) p = fmaf(sel[i], cls[i * 5 + j], p);
            if (p > best) { best = p; bj = j; }
        }
        out[b] = (float)bj;
    }
}

// ---------------- launch ----------------
extern "C" void kernel_launch(void* const* d_in, const int* in_sizes, int n_in,
                              void* d_out, int out_size) {
    const float* A1   = (const float*)d_in[0];
    const int*   rows = (const int*)  d_in[1];
    const int*   cols = (const int*)  d_in[2];
    const float* vals = (const float*)d_in[3];
    const int*   bidx = (const int*)  d_in[4];
    const float* rc   = (const float*)d_in[5];
    const float* np   = (const float*)d_in[6];
    const float* Lin1 = (const float*)d_in[7];
    const float* L1b  = (const float*)d_in[8];
    const float* g1w  = (const float*)d_in[9];
    const float* g1b  = (const float*)d_in[10];
    const float* g2w  = (const float*)d_in[11];
    const float* g2b  = (const float*)d_in[12];
    const float* wt   = (const float*)d_in[13];
    const float* wt2  = (const float*)d_in[14];
    const float* c1w  = (const float*)d_in[15];
    const float* c1b  = (const float*)d_in[16];
    const float* c2w  = (const float*)d_in[17];
    const float* c2b  = (const float*)d_in[18];
    const float* cls  = (const float*)d_in[19];
    const float* clsb = (const float*)d_in[20];
    float* out = (float*)d_out;

    float* p_la;   cudaGetSymbolAddress((void**)&p_la,   d_la);
    float* p_t1p1; cudaGetSymbolAddress((void**)&p_t1p1, d_t1p1);
    float* p_lx;   cudaGetSymbolAddress((void**)&p_lx,   d_lx);
    float* p_wcat; cudaGetSymbolAddress((void**)&p_wcat, d_Wcat);

    k0<<<1, 1>>>(rc, L1b, g1b, g2b);
    prep_wcat<<<128, 256>>>(Lin1, g1w);
    k1<<<12500, 256>>>(A1);
    sgemm<<<dim3(782, 2), 256>>>(p_la, p_wcat, p_t1p1, 256);
    k3<<<12500, 256>>>(np);
    zero_agg<<<3200, 1024>>>();
    spmm<<<200000, 256>>>(rows, cols, vals);
    k7<<<12500, 256>>>(np);
    sgemm<<<dim3(782, 1), 256>>>(p_lx, g2w, p_t1p1, 128);
    k9<<<12500, 256>>>();
    zero_agg<<<3200, 1024>>>();
    spmm<<<200000, 256>>>(rows, cols, vals);
    k11<<<12500, 256>>>();
    head<<<BB, 128>>>(bidx, wt, wt2, c1w, c1b, c2w, c2b, cls, clsb, out);
}

// round 3
// speedup vs baseline: 1.9508x; 1.9508x over previous
#include <cuda_runtime.h>
#include <math.h>
#include <stdint.h>

#define NN 100000
#define NROWS 100096   // 782 * 128, padded for tiled GEMM
#define EE 1600000
#define BB 4096
#define ML 50
#define NPAD 100352    // 98 * 1024, padded for scan

#define MIN_NORM 1e-15f
#define EPSC 1e-7f
#define MAX_NORMC 1000000.0f

// ---------------- persistent scratch (static device allocations) ----------------
__device__ float d_K, d_sqrtK;
__device__ float d_ub1[128], d_ubg1[128], d_ubg2[128];
__device__ float d_la  [(size_t)NROWS * 128];  // logmap0(a)
__device__ float d_t1p1[(size_t)NROWS * 256];  // GEMM outputs (t1 | p1) / q (stride 128)
__device__ float d_la1 [(size_t)NN * 128];     // logmap0(a1)
__device__ float d_la2 [(size_t)NN * 128];     // logmap0(a2)
__device__ float d_g   [(size_t)NN * 128];     // pre-aggregation tangent vectors
__device__ float d_agg [(size_t)NN * 128];     // segment-sum result
__device__ float d_lx  [(size_t)NROWS * 128];  // logmap0(x_1) then logmap0(x_2)
__device__ float d_Wcat[128 * 256];            // [Lin1[1:,:] | gc1_w[1:,:]]

// CSR scratch
__device__ int  d_cnt[NPAD];
__device__ int  d_rowptr[NPAD];
__device__ int  d_woff[NN];
__device__ int  d_bsum[98];
__device__ int  d_bscan[98];
__device__ int2 d_epack[EE];

// ---------------- warp helpers ----------------
__device__ __forceinline__ float wsum(float v) {
#pragma unroll
    for (int o = 16; o > 0; o >>= 1) v += __shfl_xor_sync(0xffffffffu, v, o);
    return v;
}

__device__ __forceinline__ float sdot(const float* a, const float* b, int lane) {
    float s = a[1] * b[1] + a[2] * b[2] + a[3] * b[3];
    if (lane != 0) s += a[0] * b[0];
    return wsum(s);
}

// expmap0 + proj : raw tangent (comp0 ignored) -> hyperboloid point. Returns p0.
__device__ __forceinline__ float hpoint(const float in[4], float out[4], int lane,
                                        float K, float sqrtK) {
    float ss = sdot(in, in, lane);
    float xn = fmaxf(sqrtf(ss), MIN_NORM);
    float th = xn / sqrtK;
    float s  = sqrtK * sinhf(th) / xn;
#pragma unroll
    for (int i = 0; i < 4; i++) out[i] = s * in[i];
    float ss2 = sdot(out, out, lane);
    float p0  = sqrtf(fmaxf(K + ss2, EPSC));
    if (lane == 0) out[0] = p0;
    return p0;
}

__device__ __forceinline__ void logmap0p(const float p[4], float p0, float out[4],
                                         int lane, float sqrtK) {
    float ssp = sdot(p, p, lane);
    float yn  = fmaxf(sqrtf(ssp), MIN_NORM);
    float t   = fmaxf(p0 / sqrtK, 1.0f + EPSC);
    float sc  = sqrtK * acoshf(t) / yn;
#pragma unroll
    for (int i = 0; i < 4; i++) out[i] = sc * p[i];
    if (lane == 0) out[0] = 0.0f;
}

__device__ __forceinline__ float mobius_add_pt(const float p[4], float p0,
                                               const float* __restrict__ u,
                                               float out[4], int lane,
                                               float K, float sqrtK) {
    float uv[4];
#pragma unroll
    for (int i = 0; i < 4; i++) uv[i] = u[lane * 4 + i];
    float ssp   = sdot(p, p, lane);
    float yn    = fmaxf(sqrtf(ssp), MIN_NORM);
    float du    = sdot(p, uv, lane);
    float alpha = du / (yn * sqrtK);
    float beta  = alpha * (sqrtK - p0) / yn;
    float w[4];
#pragma unroll
    for (int i = 0; i < 4; i++) w[i] = uv[i] - beta * p[i];
    float ux = sdot(p, w, lane);
    float w0 = ux / fmaxf(p0, EPSC);
    float wss   = sdot(w, w, lane);
    float md    = wss - w0 * w0;
    float normu = fminf(sqrtf(fmaxf(md, EPSC)), MAX_NORMC);
    float th    = fmaxf(normu / sqrtK, MIN_NORM);
    float ch    = coshf(th);
    float sh    = sinhf(th) / th;
#pragma unroll
    for (int i = 0; i < 4; i++) out[i] = ch * p[i] + sh * w[i];
    float rss = sdot(out, out, lane);
    float q0  = sqrtf(fmaxf(K + rss, EPSC));
    if (lane == 0) out[0] = q0;
    return q0;
}

// ---------------- K0: constants + bias tangent vectors ----------------
__device__ void bias_u(const float* b, float* u, float K, float sqrtK) {
    float ss = 0.0f;
    for (int i = 1; i < 128; i++) ss += b[i] * b[i];
    float xn = fmaxf(sqrtf(ss), MIN_NORM);
    float th = xn / sqrtK;
    float s  = sqrtK * sinhf(th) / xn;
    float y[128];
    float ss2 = 0.0f;
    for (int i = 1; i < 128; i++) { y[i] = s * b[i]; ss2 += y[i] * y[i]; }
    float x0 = sqrtf(fmaxf(K + ss2, EPSC));
    float yn = fmaxf(sqrtf(ss2), MIN_NORM);
    float t  = fmaxf(x0 / sqrtK, 1.0f + EPSC);
    float sc = sqrtK * acoshf(t) / yn;
    u[0] = 0.0f;
    for (int i = 1; i < 128; i++) u[i] = sc * y[i];
}

__global__ void k0(const float* __restrict__ rc, const float* __restrict__ b1,
                   const float* __restrict__ bg1, const float* __restrict__ bg2) {
    float c = log1pf(expf(rc[0])) + 1e-5f;
    float K = 1.0f / c, sq = sqrtf(K);
    d_K = K; d_sqrtK = sq;
    bias_u(b1,  d_ub1,  K, sq);
    bias_u(bg1, d_ubg1, K, sq);
    bias_u(bg2, d_ubg2, K, sq);
}

__global__ void prep_wcat(const float* __restrict__ Lin1, const float* __restrict__ g1w) {
    int j = blockIdx.x * 256 + threadIdx.x;
    int k = j >> 8, col = j & 255;
    d_Wcat[j] = (col < 128) ? Lin1[(k + 1) * 128 + col]
                            : g1w[(k + 1) * 128 + (col - 128)];
}

// ---------------- CSR build ----------------
__global__ void zero_cnt() {
    int i = blockIdx.x * 256 + threadIdx.x;
    if (i < NPAD) d_cnt[i] = 0;
}

__global__ void hist(const int* __restrict__ rows) {
    int e = blockIdx.x * 256 + threadIdx.x;
    if (e < EE) atomicAdd(&d_cnt[rows[e]], 1);
}

// block-level exclusive scan: 98 blocks x 1024
__global__ void __launch_bounds__(1024) scan1() {
    __shared__ int sh[1024];
    int t = threadIdx.x;
    int i = blockIdx.x * 1024 + t;
    int v = d_cnt[i];
    sh[t] = v;
    __syncthreads();
#pragma unroll
    for (int off = 1; off < 1024; off <<= 1) {
        int x = (t >= off) ? sh[t - off] : 0;
        __syncthreads();
        sh[t] += x;
        __syncthreads();
    }
    d_rowptr[i] = sh[t] - v;               // exclusive within block
    if (t == 1023) d_bsum[blockIdx.x] = sh[1023];
}

__global__ void __launch_bounds__(128) scan2() {
    __shared__ int sh[128];
    int t = threadIdx.x;
    int v = (t < 98) ? d_bsum[t] : 0;
    sh[t] = v;
    __syncthreads();
#pragma unroll
    for (int off = 1; off < 128; off <<= 1) {
        int x = (t >= off) ? sh[t - off] : 0;
        __syncthreads();
        sh[t] += x;
        __syncthreads();
    }
    if (t < 98) d_bscan[t] = sh[t] - v;    // exclusive
}

__global__ void scan3() {
    int i = blockIdx.x * 256 + threadIdx.x;
    if (i < NPAD) {
        int v = d_rowptr[i] + d_bscan[i >> 10];
        d_rowptr[i] = v;
        if (i < NN) d_woff[i] = v;
    }
}

__global__ void scatter(const int* __restrict__ rows, const int* __restrict__ cols,
                        const float* __restrict__ vals) {
    int e = blockIdx.x * 256 + threadIdx.x;
    if (e < EE) {
        int r = rows[e];
        int pos = atomicAdd(&d_woff[r], 1);
        d_epack[pos] = make_int2(cols[e], __float_as_int(vals[e]));
    }
}

// ---------------- K1: la = logmap0(proj(expmap0(A1 spatial))) ----------------
__global__ void __launch_bounds__(256) k1(const float* __restrict__ A1) {
    int node = blockIdx.x * 8 + (threadIdx.x >> 5);
    int lane = threadIdx.x & 31;
    float K = d_K, sq = d_sqrtK;
    const float* row = A1 + (size_t)node * 129 + 1;
    float x[4];
#pragma unroll
    for (int i = 0; i < 4; i++) x[i] = row[lane * 4 + i];
    float ss = wsum(x[0]*x[0] + x[1]*x[1] + x[2]*x[2] + x[3]*x[3]);
    float xn = fmaxf(sqrtf(ss), MIN_NORM);
    float th = xn / sq;
    float s  = sq * sinhf(th) / xn;
    float y[4];
#pragma unroll
    for (int i = 0; i < 4; i++) y[i] = s * x[i];
    float ss2 = wsum(y[0]*y[0] + y[1]*y[1] + y[2]*y[2] + y[3]*y[3]);
    float x0 = sqrtf(fmaxf(K + ss2, EPSC));
    float yn = fmaxf(sqrtf(ss2), MIN_NORM);
    float t  = fmaxf(x0 / sq, 1.0f + EPSC);
    float sc = sq * acoshf(t) / yn;
    float* o = d_la + (size_t)node * 128 + lane * 4;
#pragma unroll
    for (int i = 0; i < 4; i++) o[i] = sc * y[i];
}

// ---------------- register-blocked SGEMM: (NROWS,128) @ (128,N) ----------------
__global__ void __launch_bounds__(256) sgemm(const float* __restrict__ A,
                                             const float* __restrict__ W,
                                             float* __restrict__ C, int N) {
    __shared__ float sA[32][128];
    __shared__ float sB[32][128];

    int tid = threadIdx.x;
    int tx = tid & 15;
    int ty = tid >> 4;
    int r0 = blockIdx.x * 128;
    int n0 = blockIdx.y * 128;

    int arow = tid >> 1;
    int af   = (tid & 1) * 4;
    int brow = tid >> 3;
    int bf   = (tid & 7) * 4;

    float acc[8][8];
#pragma unroll
    for (int i = 0; i < 8; i++)
#pragma unroll
        for (int j = 0; j < 8; j++) acc[i][j] = 0.0f;

    for (int k0 = 0; k0 < 128; k0 += 32) {
#pragma unroll
        for (int i = 0; i < 4; i++) {
            int f = af + i;
            float4 v = *(const float4*)(A + (size_t)(r0 + arow) * 128 + k0 + f * 4);
            sA[f * 4 + 0][arow] = v.x;
            sA[f * 4 + 1][arow] = v.y;
            sA[f * 4 + 2][arow] = v.z;
            sA[f * 4 + 3][arow] = v.w;
        }
#pragma unroll
        for (int i = 0; i < 4; i++) {
            int f = bf + i;
            float4 v = *(const float4*)(W + (size_t)(k0 + brow) * N + n0 + f * 4);
            *(float4*)&sB[brow][f * 4] = v;
        }
        __syncthreads();

#pragma unroll 8
        for (int kk = 0; kk < 32; kk++) {
            float a[8], b[8];
            *(float4*)&a[0] = *(const float4*)&sA[kk][ty * 8];
            *(float4*)&a[4] = *(const float4*)&sA[kk][ty * 8 + 4];
            *(float4*)&b[0] = *(const float4*)&sB[kk][tx * 8];
            *(float4*)&b[4] = *(const float4*)&sB[kk][tx * 8 + 4];
#pragma unroll
            for (int i = 0; i < 8; i++)
#pragma unroll
                for (int j = 0; j < 8; j++)
                    acc[i][j] = fmaf(a[i], b[j], acc[i][j]);
        }
        __syncthreads();
    }

#pragma unroll
    for (int i = 0; i < 8; i++) {
        float* dst = C + (size_t)(r0 + ty * 8 + i) * N + n0 + tx * 8;
        *(float4*)dst       = *(float4*)&acc[i][0];
        *(float4*)(dst + 4) = *(float4*)&acc[i][4];
    }
}

// ---------------- K3 ----------------
__global__ void __launch_bounds__(256) k3(const float* __restrict__ nparam) {
    int node = blockIdx.x * 8 + (threadIdx.x >> 5);
    int lane = threadIdx.x & 31;
    float K = d_K, sq = d_sqrtK;
    const float* tr = d_t1p1 + (size_t)node * 256;
    float t[4], p[4];
#pragma unroll
    for (int i = 0; i < 4; i++) { t[i] = tr[lane * 4 + i]; p[i] = tr[128 + lane * 4 + i]; }

    float P[4];  float p0 = hpoint(t, P, lane, K, sq);
    float Aa[4]; float a0 = mobius_add_pt(P, p0, d_ub1, Aa, lane, K, sq);
    float l1[4]; logmap0p(Aa, a0, l1, lane, sq);
    float* o1 = d_la1 + (size_t)node * 128 + lane * 4;
#pragma unroll
    for (int i = 0; i < 4; i++) o1[i] = l1[i];

    float n = nparam[node];
    float v2[4];
#pragma unroll
    for (int i = 0; i < 4; i++) v2[i] = n * l1[i];
    float A2[4]; float a20 = hpoint(v2, A2, lane, K, sq);
    float l2[4]; logmap0p(A2, a20, l2, lane, sq);
    float* o2 = d_la2 + (size_t)node * 128 + lane * 4;
#pragma unroll
    for (int i = 0; i < 4; i++) o2[i] = l2[i];

    float Pg[4]; float pg0 = hpoint(p, Pg, lane, K, sq);
    float G[4];  float g0  = mobius_add_pt(Pg, pg0, d_ubg1, G, lane, K, sq);
    float lg[4]; logmap0p(G, g0, lg, lane, sq);
    float* og = d_g + (size_t)node * 128 + lane * 4;
#pragma unroll
    for (int i = 0; i < 4; i++) og[i] = lg[i];
}

// ---------------- CSR gather-reduce SpMM: one warp per row ----------------
__global__ void __launch_bounds__(256) spmm_csr() {
    int row = blockIdx.x * 8 + (threadIdx.x >> 5);
    int lane = threadIdx.x & 31;
    if (row >= NN) return;
    int s = d_rowptr[row];
    int e = d_rowptr[row + 1];
    float4 acc = make_float4(0.f, 0.f, 0.f, 0.f);
    int i = s;
    for (; i + 2 <= e; i += 2) {
        int2 p0 = d_epack[i];
        int2 p1 = d_epack[i + 1];
        float4 g0 = ((const float4*)(d_g + (size_t)p0.x * 128))[lane];
        float4 g1 = ((const float4*)(d_g + (size_t)p1.x * 128))[lane];
        float v0 = __int_as_float(p0.y);
        float v1 = __int_as_float(p1.y);
        acc.x = fmaf(v0, g0.x, fmaf(v1, g1.x, acc.x));
        acc.y = fmaf(v0, g0.y, fmaf(v1, g1.y, acc.y));
        acc.z = fmaf(v0, g0.z, fmaf(v1, g1.z, acc.z));
        acc.w = fmaf(v0, g0.w, fmaf(v1, g1.w, acc.w));
    }
    if (i < e) {
        int2 p0 = d_epack[i];
        float4 g0 = ((const float4*)(d_g + (size_t)p0.x * 128))[lane];
        float v0 = __int_as_float(p0.y);
        acc.x = fmaf(v0, g0.x, acc.x);
        acc.y = fmaf(v0, g0.y, acc.y);
        acc.z = fmaf(v0, g0.z, acc.z);
        acc.w = fmaf(v0, g0.w, acc.w);
    }
    ((float4*)(d_agg + (size_t)row * 128))[lane] = acc;
}

// ---------------- K7 ----------------
__global__ void __launch_bounds__(256) k7(const float* __restrict__ nparam) {
    int node = blockIdx.x * 8 + (threadIdx.x >> 5);
    int lane = threadIdx.x & 31;
    float K = d_K, sq = d_sqrtK;
    const float* ar = d_agg + (size_t)node * 128 + lane * 4;
    float v[4];
#pragma unroll
    for (int i = 0; i < 4; i++) v[i] = ar[i];
    float X[4]; float x0 = hpoint(v, X, lane, K, sq);
    float l[4]; logmap0p(X, x0, l, lane, sq);
    float n = 1.0f - nparam[node];
    float v2[4];
#pragma unroll
    for (int i = 0; i < 4; i++) v2[i] = n * l[i];
    float X2[4]; float x20 = hpoint(v2, X2, lane, K, sq);
    float l2[4]; logmap0p(X2, x20, l2, lane, sq);
    const float* a2r = d_la2 + (size_t)node * 128 + lane * 4;
    float w[4];
#pragma unroll
    for (int i = 0; i < 4; i++) w[i] = l2[i] + a2r[i];
    float X3[4]; float x30 = hpoint(w, X3, lane, K, sq);
    float lx[4]; logmap0p(X3, x30, lx, lane, sq);
    float* o = d_lx + (size_t)node * 128 + lane * 4;
#pragma unroll
    for (int i = 0; i < 4; i++) o[i] = lx[i];
}

// ---------------- K9 ----------------
__global__ void __launch_bounds__(256) k9() {
    int node = blockIdx.x * 8 + (threadIdx.x >> 5);
    int lane = threadIdx.x & 31;
    float K = d_K, sq = d_sqrtK;
    const float* qr = d_t1p1 + (size_t)node * 128 + lane * 4;
    float q[4];
#pragma unroll
    for (int i = 0; i < 4; i++) q[i] = qr[i];
    float X[4]; float x0 = hpoint(q, X, lane, K, sq);
    float G[4]; float g0 = mobius_add_pt(X, x0, d_ubg2, G, lane, K, sq);
    float lg[4]; logmap0p(G, g0, lg, lane, sq);
    float* o = d_g + (size_t)node * 128 + lane * 4;
#pragma unroll
    for (int i = 0; i < 4; i++) o[i] = lg[i];
}

// ---------------- K11 ----------------
__global__ void __launch_bounds__(256) k11() {
    int node = blockIdx.x * 8 + (threadIdx.x >> 5);
    int lane = threadIdx.x & 31;
    float K = d_K, sq = d_sqrtK;
    const float* ar = d_agg + (size_t)node * 128 + lane * 4;
    float v[4];
#pragma unroll
    for (int i = 0; i < 4; i++) v[i] = ar[i];
    float X[4]; float x0 = hpoint(v, X, lane, K, sq);
    float lx[4]; logmap0p(X, x0, lx, lane, sq);
    float* o = d_lx + (size_t)node * 128 + lane * 4;
#pragma unroll
    for (int i = 0; i < 4; i++) o[i] = lx[i];
}

// ---------------- head ----------------
__global__ void __launch_bounds__(128) head(const int* __restrict__ bidx,
                                            const float* __restrict__ wt,
                                            const float* __restrict__ wt2,
                                            const float* __restrict__ c1w,
                                            const float* __restrict__ c1b,
                                            const float* __restrict__ c2w,
                                            const float* __restrict__ c2b,
                                            const float* __restrict__ cls,
                                            const float* __restrict__ clsb,
                                            float* __restrict__ out) {
    int b = blockIdx.x;
    int d = threadIdx.x;
    __shared__ float sg2[128], sg3[128], sel[100];
    float g2 = 0.0f, g3 = 0.0f;
    const int* bi = bidx + (size_t)b * ML;
    for (int l = 0; l < ML; l++) {
        int idx = bi[l];
        float w1 = c1w[l], w2 = c2w[l];
        g2 = fmaf(w1, d_lx [(size_t)idx * 128 + d], g2);
        g3 = fmaf(w2, d_la1[(size_t)idx * 128 + d], g3);
    }
    sg2[d] = g2; sg3[d] = g3;
    __syncthreads();
    if (d < ML) {
        float s2 = c1b[0], s3 = c2b[0];
        for (int k = 0; k < 128; k++) {
            s2 = fmaf(sg2[k], wt [k * ML + d], s2);
            s3 = fmaf(sg3[k], wt2[k * ML + d], s3);
        }
        sel[d]      = s2;
        sel[ML + d] = s3;
        out[BB + (size_t)b * 100 + d]      = s2;
        out[BB + (size_t)b * 100 + ML + d] = s3;
    }
    __syncthreads();
    if (d == 0) {
        float best = -3.4e38f;
        int bj = 0;
        for (int j = 0; j < 5; j++) {
            float p = clsb[j];
            for (int i = 0; i < 100; i++) p = fmaf(sel[i], cls[i * 5 + j], p);
            if (p > best) { best = p; bj = j; }
        }
        out[b] = (float)bj;
    }
}

// ---------------- launch ----------------
extern "C" void kernel_launch(void* const* d_in, const int* in_sizes, int n_in,
                              void* d_out, int out_size) {
    const float* A1   = (const float*)d_in[0];
    const int*   rows = (const int*)  d_in[1];
    const int*   cols = (const int*)  d_in[2];
    const float* vals = (const float*)d_in[3];
    const int*   bidx = (const int*)  d_in[4];
    const float* rc   = (const float*)d_in[5];
    const float* np   = (const float*)d_in[6];
    const float* Lin1 = (const float*)d_in[7];
    const float* L1b  = (const float*)d_in[8];
    const float* g1w  = (const float*)d_in[9];
    const float* g1b  = (const float*)d_in[10];
    const float* g2w  = (const float*)d_in[11];
    const float* g2b  = (const float*)d_in[12];
    const float* wt   = (const float*)d_in[13];
    const float* wt2  = (const float*)d_in[14];
    const float* c1w  = (const float*)d_in[15];
    const float* c1b  = (const float*)d_in[16];
    const float* c2w  = (const float*)d_in[17];
    const float* c2b  = (const float*)d_in[18];
    const float* cls  = (const float*)d_in[19];
    const float* clsb = (const float*)d_in[20];
    float* out = (float*)d_out;

    float* p_la;   cudaGetSymbolAddress((void**)&p_la,   d_la);
    float* p_t1p1; cudaGetSymbolAddress((void**)&p_t1p1, d_t1p1);
    float* p_lx;   cudaGetSymbolAddress((void**)&p_lx,   d_lx);
    float* p_wcat; cudaGetSymbolAddress((void**)&p_wcat, d_Wcat);

    k0<<<1, 1>>>(rc, L1b, g1b, g2b);
    prep_wcat<<<128, 256>>>(Lin1, g1w);

    // CSR build (once, reused by both aggregation passes)
    zero_cnt<<<(NPAD + 255) / 256, 256>>>();
    hist<<<(EE + 255) / 256, 256>>>(rows);
    scan1<<<98, 1024>>>();
    scan2<<<1, 128>>>();
    scan3<<<(NPAD + 255) / 256, 256>>>();
    scatter<<<(EE + 255) / 256, 256>>>(rows, cols, vals);

    k1<<<12500, 256>>>(A1);
    sgemm<<<dim3(782, 2), 256>>>(p_la, p_wcat, p_t1p1, 256);
    k3<<<12500, 256>>>(np);
    spmm_csr<<<12500, 256>>>();
    k7<<<12500, 256>>>(np);
    sgemm<<<dim3(782, 1), 256>>>(p_lx, g2w, p_t1p1, 128);
    k9<<<12500, 256>>>();
    spmm_csr<<<12500, 256>>>();
    k11<<<12500, 256>>>();
    head<<<BB, 128>>>(bidx, wt, wt2, c1w, c1b, c2w, c2b, cls, clsb, out);
}